// round 14
// baseline (speedup 1.0000x reference)
#include <cuda_runtime.h>
#include <cstdint>

typedef unsigned long long ull;
#define THREADS 512

// tile: 14x14 low-res -> 28x28 output (v13 persistent, software-pipelined)
// smem: xb float [16 ic][17 r][18 pad]        @ 0      = 19584 B
//       wb ull2  [16 ic][8 op][5 pairs]       @ 19584  = 10240 B
//       z2 ull   [8 op][32 zr][36 (zeta,pad)] @ 29824  = 73728 B
#define XB_R   18
#define WB_OFF 19584
#define Z2_OFF 29824
#define Z2_ROW 36
#define Z2_OP  (32 * Z2_ROW)
#define SMEM_BYTES 103552

#define NTILES 1444        // 4 batch * 361 spatial
#define NSLOTS 37          // CTAs per group (296 = 8 groups * 37)

__device__ __forceinline__ ull pack2(float v) {
    ull r; asm("mov.b64 %0, {%1, %1};" : "=l"(r) : "f"(v)); return r;
}
__device__ __forceinline__ ull packf2(float a, float b) {
    ull r; asm("mov.b64 %0, {%1, %2};" : "=l"(r) : "f"(a), "f"(b)); return r;
}
__device__ __forceinline__ void fma2(ull &acc, ull a, ull b) {
    asm("fma.rn.f32x2 %0, %1, %2, %0;" : "+l"(acc) : "l"(a), "l"(b));
}

// stage-1 loader: tile (a0,b0) of batch n -> xb
__device__ __forceinline__ void load_xtile(float* xb, const float* xg,
                                           int a0, int b0, int tid) {
    for (int i = tid; i < 16 * 17 * 17; i += THREADS) {
        int c = i % 17;
        int rr = (i / 17) % 17;
        int ic = i / 289;
        int gm = a0 - 2 + rr, gq = b0 - 2 + c;
        float v = (gm >= 0 && gm < 256 && gq >= 0 && gq < 256)
                    ? xg[ic * 65536 + gm * 256 + gq] : 0.f;
        xb[(ic * 17 + rr) * XB_R + c] = v;
    }
}

__global__ __launch_bounds__(THREADS, 2)
void conv_resample_v14(const float* __restrict__ x, const float* __restrict__ f,
                       const float* __restrict__ w, float* __restrict__ out) {
    extern __shared__ char sm[];
    float* xb = (float*)sm;
    ulonglong2* wb = (ulonglong2*)(sm + WB_OFF);
    ull* zb = (ull*)(sm + Z2_OFF);

    const int tid = threadIdx.x;
    const int wid = tid >> 5, ln = tid & 31;
    const int g = blockIdx.x & 7;
    const int slot = blockIdx.x >> 3;
    const float* xbase = x + (size_t)g * 16 * 65536;

    // ---- one-time: weights as oc-pair f32x2 in paired ull2 [ic][op][5] ----
    {
        const int lt[5] = {0, 2, 7, 3, 4};
        const int ht[5] = {1, 6, 8, 5, 0};
        const float* wgp = w + (size_t)g * 16 * 144;
        for (int i = tid; i < 16 * 8 * 5; i += THREADS) {
            int j = i % 5;
            int op = (i / 5) & 7;
            int ic = i / 40;
            const float* w0 = wgp + (op * 2 + 0) * 144 + ic * 9;
            const float* w1 = wgp + (op * 2 + 1) * 144 + ic * 9;
            ulonglong2 pr;
            pr.x = packf2(w0[lt[j]], w1[lt[j]]);
            pr.y = (j == 4) ? 0ull : packf2(w0[ht[j]], w1[ht[j]]);
            wb[i] = pr;
        }
    }
    const float f0 = __ldg(f), f1 = __ldg(f + 1), f2 = __ldg(f + 2), f3 = __ldg(f + 3);
    const ull gq0 = pack2(2.f * f3), gq1 = pack2(2.f * f2),
              gq2 = pack2(2.f * f1), gq3 = pack2(2.f * f0);

    // ---- prologue: load first tile ----
    {
        const int t0 = slot;
        const int n = t0 / 361;
        const int sp = t0 - n * 361;
        const int rt = sp / 19, ct = sp - rt * 19;
        load_xtile(xb, xbase + (size_t)n * 128 * 65536, rt * 14, ct * 14, tid);
    }
    __syncthreads();

    // ---- pipelined persistent loop ----
#pragma unroll 1
    for (int t = slot; t < NTILES; t += NSLOTS) {
        const int n = t / 361;
        const int sp = t - n * 361;
        const int rt = sp / 19, ct = sp - rt * 19;
        const int a0 = rt * 14, b0 = ct * 14;

        // ---- stage 2: xb -> zb ----
        {
            const int opg = wid & 3, rb = wid >> 2;
            const int op = opg * 2 + (ln >> 4);
            const int pc = ln & 15;
            const int ar0 = rb * 4;

            ull acc[4][4];
#pragma unroll
            for (int r = 0; r < 4; ++r) { acc[r][0] = acc[r][1] = acc[r][2] = acc[r][3] = 0ull; }

#pragma unroll 4
            for (int ic = 0; ic < 16; ++ic) {
                const ulonglong2* wp = wb + (ic * 8 + op) * 5;
                ulonglong2 W0 = wp[0];   // (w0, w1)
                ulonglong2 W1 = wp[1];   // (w2, w6)
                ulonglong2 W2 = wp[2];   // (w7, w8)
                ulonglong2 W3 = wp[3];   // (w3, w5)
                ull W4 = wp[4].x;        // w4
                const float* xr = xb + (ic * 17 + ar0) * XB_R + pc;
                ull xa = pack2(xr[0]), xbv = pack2(xr[1]);
#pragma unroll
                for (int r = 0; r < 4; ++r) {
                    ull ya = pack2(xr[(r + 1) * XB_R]);
                    ull yb = pack2(xr[(r + 1) * XB_R + 1]);
                    fma2(acc[r][0], xa,  W0.x); fma2(acc[r][0], xbv, W1.x);
                    fma2(acc[r][0], ya,  W1.y); fma2(acc[r][0], yb,  W2.y);
                    fma2(acc[r][1], xbv, W0.y); fma2(acc[r][1], yb,  W2.x);
                    fma2(acc[r][2], ya,  W3.x); fma2(acc[r][2], yb,  W3.y);
                    fma2(acc[r][3], yb,  W4);
                    xa = ya; xbv = yb;
                }
            }
            ull* zo = zb + (size_t)op * Z2_OP + 2 * pc;
#pragma unroll
            for (int r = 0; r < 4; ++r) {
                int zr0 = 2 * (ar0 + r);
                ulonglong2 e0; e0.x = acc[r][0]; e0.y = acc[r][1];   // py0: (px0, px1)
                ulonglong2 e1; e1.x = acc[r][2]; e1.y = acc[r][3];   // py1
                *(ulonglong2*)(zo + (size_t)zr0 * Z2_ROW)       = e0;
                *(ulonglong2*)(zo + (size_t)(zr0 + 1) * Z2_ROW) = e1;
            }
        }
        __syncthreads();

        // ---- stage 3 (zb -> gmem) ----
        {
            const int op3 = wid & 7, rh = wid >> 3;
            const int oy0 = rh * 14;
            const bool lane_ok = (ln < 28);
            const int oxc = lane_ok ? ln : 27;

            const ull* zp = zb + (size_t)op3 * Z2_OP + (size_t)(oy0 + 1) * Z2_ROW + (oxc + 1);
            ull tb0, tb1, tb2;
            { ull tt = 0; fma2(tt, zp[0], gq0); fma2(tt, zp[1], gq1);
              fma2(tt, zp[2], gq2); fma2(tt, zp[3], gq3); tb0 = tt; zp += Z2_ROW; }
            { ull tt = 0; fma2(tt, zp[0], gq0); fma2(tt, zp[1], gq1);
              fma2(tt, zp[2], gq2); fma2(tt, zp[3], gq3); tb1 = tt; zp += Z2_ROW; }
            { ull tt = 0; fma2(tt, zp[0], gq0); fma2(tt, zp[1], gq1);
              fma2(tt, zp[2], gq2); fma2(tt, zp[3], gq3); tb2 = tt; zp += Z2_ROW; }

            const bool col_ok = lane_ok && (2 * b0 + ln < 512);
            float* og = out + ((size_t)(n * 128 + g * 16 + op3 * 2)) * 262144
                            + (size_t)(2 * a0) * 512 + 2 * b0;

#pragma unroll 7
            for (int oyl = 0; oyl < 14; ++oyl) {
                ull tt = 0;
                fma2(tt, zp[0], gq0); fma2(tt, zp[1], gq1);
                fma2(tt, zp[2], gq2); fma2(tt, zp[3], gq3);
                zp += Z2_ROW;
                ull y = 0;
                fma2(y, tb0, gq0); fma2(y, tb1, gq1);
                fma2(y, tb2, gq2); fma2(y, tt, gq3);
                tb0 = tb1; tb1 = tb2; tb2 = tt;
                int oy = oy0 + oyl;
                if (col_ok && (2 * a0 + oy < 512)) {
                    float2 yy = *(float2*)&y;
                    size_t o = (size_t)oy * 512 + ln;
                    og[o] = yy.x;
                    og[o + 262144] = yy.y;
                }
            }
        }

        // ---- stage 1 for next tile (gmem -> xb), same phase as stage 3 ----
        {
            int tn = t + NSLOTS;
            if (tn < NTILES) {
                const int nn = tn / 361;
                const int spn = tn - nn * 361;
                const int rtn = spn / 19, ctn = spn - rtn * 19;
                load_xtile(xb, xbase + (size_t)nn * 128 * 65536, rtn * 14, ctn * 14, tid);
            }
        }
        __syncthreads();
    }
}

extern "C" void kernel_launch(void* const* d_in, const int* in_sizes, int n_in,
                              void* d_out, int out_size) {
    const float* x = (const float*)d_in[0];
    const float* f = (const float*)d_in[1];
    const float* w = (const float*)d_in[2];
    float* out = (float*)d_out;

    cudaFuncSetAttribute(conv_resample_v14,
                         cudaFuncAttributeMaxDynamicSharedMemorySize, SMEM_BYTES);
    conv_resample_v14<<<296, THREADS, SMEM_BYTES>>>(x, f, w, out);   // 2 CTAs/SM, persistent
}

// round 15
// speedup vs baseline: 1.3699x; 1.3699x over previous
#include <cuda_runtime.h>
#include <cstdint>

typedef unsigned long long ull;
#define THREADS 512

// tile: 14x14 low-res -> 28x28 output (v13 persistent structure + fast paths)
// smem: xb float [16 ic][17 r][18 pad]        @ 0      = 19584 B
//       wb ull2  [16 ic][8 op][5 pairs]       @ 19584  = 10240 B
//       z2 ull   [8 op][32 zr][36 (zeta,pad)] @ 29824  = 73728 B
#define XB_R   18
#define WB_OFF 19584
#define Z2_OFF 29824
#define Z2_ROW 36
#define Z2_OP  (32 * Z2_ROW)
#define SMEM_BYTES 103552

#define NTILES 1444        // 4 batch * 361 spatial
#define NSLOTS 37          // CTAs per group (296 = 8 groups * 37)

__device__ __forceinline__ ull pack2(float v) {
    ull r; asm("mov.b64 %0, {%1, %1};" : "=l"(r) : "f"(v)); return r;
}
__device__ __forceinline__ ull packf2(float a, float b) {
    ull r; asm("mov.b64 %0, {%1, %2};" : "=l"(r) : "f"(a), "f"(b)); return r;
}
__device__ __forceinline__ void fma2(ull &acc, ull a, ull b) {
    asm("fma.rn.f32x2 %0, %1, %2, %0;" : "+l"(acc) : "l"(a), "l"(b));
}

__global__ __launch_bounds__(THREADS, 2)
void conv_resample_v15(const float* __restrict__ x, const float* __restrict__ f,
                       const float* __restrict__ w, float* __restrict__ out) {
    extern __shared__ char sm[];
    float* xb = (float*)sm;
    ulonglong2* wb = (ulonglong2*)(sm + WB_OFF);
    ull* zb = (ull*)(sm + Z2_OFF);

    const int tid = threadIdx.x;
    const int wid = tid >> 5, ln = tid & 31;
    const int g = blockIdx.x & 7;
    const int slot = blockIdx.x >> 3;

    // ---- one-time: weights as oc-pair f32x2 in paired ull2 [ic][op][5] ----
    {
        const int lt[5] = {0, 2, 7, 3, 4};
        const int ht[5] = {1, 6, 8, 5, 0};
        const float* wgp = w + (size_t)g * 16 * 144;
        for (int i = tid; i < 16 * 8 * 5; i += THREADS) {
            int j = i % 5;
            int op = (i / 5) & 7;
            int ic = i / 40;
            const float* w0 = wgp + (op * 2 + 0) * 144 + ic * 9;
            const float* w1 = wgp + (op * 2 + 1) * 144 + ic * 9;
            ulonglong2 pr;
            pr.x = packf2(w0[lt[j]], w1[lt[j]]);
            pr.y = (j == 4) ? 0ull : packf2(w0[ht[j]], w1[ht[j]]);
            wb[i] = pr;
        }
    }
    const float f0 = __ldg(f), f1 = __ldg(f + 1), f2 = __ldg(f + 2), f3 = __ldg(f + 3);
    const ull gq0 = pack2(2.f * f3), gq1 = pack2(2.f * f2),
              gq2 = pack2(2.f * f1), gq3 = pack2(2.f * f0);

    // ---- persistent tile loop ----
#pragma unroll 1
    for (int t = slot; t < NTILES; t += NSLOTS) {
        const int n = t / 361;
        const int sp = t - n * 361;
        const int rt = sp / 19, ct = sp - rt * 19;
        const int a0 = rt * 14, b0 = ct * 14;
        const bool interior = (rt >= 1) & (rt <= 17) & (ct >= 1) & (ct <= 17);
        const bool safe_out = (rt < 18) & (ct < 18);

        // ---- stage 1: x tile [16 ic][17][17] ----
        const float* xg = x + ((size_t)(n * 128 + g * 16)) * 65536;
        if (interior) {
            // no bounds checks: gm in [12,252], gq in [12,252]
            const float* xs = xg + (a0 - 2) * 256 + (b0 - 2);
#pragma unroll 1
            for (int i = tid; i < 16 * 17 * 17; i += THREADS) {
                int c = i % 17;
                int rr = (i / 17) % 17;
                int ic = i / 289;
                xb[(ic * 17 + rr) * XB_R + c] = xs[ic * 65536 + rr * 256 + c];
            }
        } else {
#pragma unroll 1
            for (int i = tid; i < 16 * 17 * 17; i += THREADS) {
                int c = i % 17;
                int rr = (i / 17) % 17;
                int ic = i / 289;
                int gm = a0 - 2 + rr, gq = b0 - 2 + c;
                float v = (gm >= 0 && gm < 256 && gq >= 0 && gq < 256)
                            ? xg[ic * 65536 + gm * 256 + gq] : 0.f;
                xb[(ic * 17 + rr) * XB_R + c] = v;
            }
        }
        __syncthreads();

        // ---- stage 2: 16 units = (4 op-groups) x (4 row-blocks); lane = (op-half, 16 cols) ----
        {
            const int opg = wid & 3, rb = wid >> 2;
            const int op = opg * 2 + (ln >> 4);
            const int pc = ln & 15;
            const int ar0 = rb * 4;

            ull acc[4][4];
#pragma unroll
            for (int r = 0; r < 4; ++r) { acc[r][0] = acc[r][1] = acc[r][2] = acc[r][3] = 0ull; }

#pragma unroll 4
            for (int ic = 0; ic < 16; ++ic) {
                const ulonglong2* wp = wb + (ic * 8 + op) * 5;
                ulonglong2 W0 = wp[0];   // (w0, w1)
                ulonglong2 W1 = wp[1];   // (w2, w6)
                ulonglong2 W2 = wp[2];   // (w7, w8)
                ulonglong2 W3 = wp[3];   // (w3, w5)
                ull W4 = wp[4].x;        // w4
                const float* xr = xb + (ic * 17 + ar0) * XB_R + pc;
                ull xa = pack2(xr[0]), xbv = pack2(xr[1]);
#pragma unroll
                for (int r = 0; r < 4; ++r) {
                    ull ya = pack2(xr[(r + 1) * XB_R]);
                    ull yb = pack2(xr[(r + 1) * XB_R + 1]);
                    fma2(acc[r][0], xa,  W0.x); fma2(acc[r][0], xbv, W1.x);
                    fma2(acc[r][0], ya,  W1.y); fma2(acc[r][0], yb,  W2.y);
                    fma2(acc[r][1], xbv, W0.y); fma2(acc[r][1], yb,  W2.x);
                    fma2(acc[r][2], ya,  W3.x); fma2(acc[r][2], yb,  W3.y);
                    fma2(acc[r][3], yb,  W4);
                    xa = ya; xbv = yb;
                }
            }
            ull* zo = zb + (size_t)op * Z2_OP + 2 * pc;
#pragma unroll
            for (int r = 0; r < 4; ++r) {
                int zr0 = 2 * (ar0 + r);
                ulonglong2 e0; e0.x = acc[r][0]; e0.y = acc[r][1];   // py0: (px0, px1)
                ulonglong2 e1; e1.x = acc[r][2]; e1.y = acc[r][3];   // py1
                *(ulonglong2*)(zo + (size_t)zr0 * Z2_ROW)       = e0;
                *(ulonglong2*)(zo + (size_t)(zr0 + 1) * Z2_ROW) = e1;
            }
        }
        __syncthreads();

        // ---- stage 3: vertical FIR register ring; warp = (op, row-half), lane = out col ----
        {
            const int op3 = wid & 7, rh = wid >> 3;
            const int oy0 = rh * 14;
            const bool lane_ok = (ln < 28);
            const int oxc = lane_ok ? ln : 27;

            const ull* zp = zb + (size_t)op3 * Z2_OP + (size_t)(oy0 + 1) * Z2_ROW + (oxc + 1);
            ull tb0, tb1, tb2;
            { ull tt = 0; fma2(tt, zp[0], gq0); fma2(tt, zp[1], gq1);
              fma2(tt, zp[2], gq2); fma2(tt, zp[3], gq3); tb0 = tt; zp += Z2_ROW; }
            { ull tt = 0; fma2(tt, zp[0], gq0); fma2(tt, zp[1], gq1);
              fma2(tt, zp[2], gq2); fma2(tt, zp[3], gq3); tb1 = tt; zp += Z2_ROW; }
            { ull tt = 0; fma2(tt, zp[0], gq0); fma2(tt, zp[1], gq1);
              fma2(tt, zp[2], gq2); fma2(tt, zp[3], gq3); tb2 = tt; zp += Z2_ROW; }

            float* og = out + ((size_t)(n * 128 + g * 16 + op3 * 2)) * 262144
                            + (size_t)(2 * a0) * 512 + 2 * b0;

            if (safe_out) {
                // all 28 output rows/cols in range: unconditional stores for ln<28
#pragma unroll 7
                for (int oyl = 0; oyl < 14; ++oyl) {
                    ull tt = 0;
                    fma2(tt, zp[0], gq0); fma2(tt, zp[1], gq1);
                    fma2(tt, zp[2], gq2); fma2(tt, zp[3], gq3);
                    zp += Z2_ROW;
                    ull y = 0;
                    fma2(y, tb0, gq0); fma2(y, tb1, gq1);
                    fma2(y, tb2, gq2); fma2(y, tt, gq3);
                    tb0 = tb1; tb1 = tb2; tb2 = tt;
                    if (lane_ok) {
                        float2 yy = *(float2*)&y;
                        size_t o = (size_t)(oy0 + oyl) * 512 + ln;
                        og[o] = yy.x;
                        og[o + 262144] = yy.y;
                    }
                }
            } else {
                const bool col_ok = lane_ok && (2 * b0 + ln < 512);
#pragma unroll 7
                for (int oyl = 0; oyl < 14; ++oyl) {
                    ull tt = 0;
                    fma2(tt, zp[0], gq0); fma2(tt, zp[1], gq1);
                    fma2(tt, zp[2], gq2); fma2(tt, zp[3], gq3);
                    zp += Z2_ROW;
                    ull y = 0;
                    fma2(y, tb0, gq0); fma2(y, tb1, gq1);
                    fma2(y, tb2, gq2); fma2(y, tt, gq3);
                    tb0 = tb1; tb1 = tb2; tb2 = tt;
                    int oy = oy0 + oyl;
                    if (col_ok && (2 * a0 + oy < 512)) {
                        float2 yy = *(float2*)&y;
                        size_t o = (size_t)oy * 512 + ln;
                        og[o] = yy.x;
                        og[o + 262144] = yy.y;
                    }
                }
            }
        }
        __syncthreads();   // protect xb (next stage1) and zb (next stage2)
    }
}

extern "C" void kernel_launch(void* const* d_in, const int* in_sizes, int n_in,
                              void* d_out, int out_size) {
    const float* x = (const float*)d_in[0];
    const float* f = (const float*)d_in[1];
    const float* w = (const float*)d_in[2];
    float* out = (float*)d_out;

    cudaFuncSetAttribute(conv_resample_v15,
                         cudaFuncAttributeMaxDynamicSharedMemorySize, SMEM_BYTES);
    conv_resample_v15<<<296, THREADS, SMEM_BYTES>>>(x, f, w, out);   // 2 CTAs/SM, persistent
}